// round 4
// baseline (speedup 1.0000x reference)
#include <cuda_runtime.h>
#include <cuda_bf16.h>

#define B_ 64
#define S_ 512
#define I_ 512
#define H_ 1024
#define O_ 512

// ---------------------------------------------------------------------------
// Static device scratch (no allocations anywhere)
// ---------------------------------------------------------------------------
__device__ float g_U[(S_ - 1) * B_ * H_];   // U[t][b][j]; later reused as logits[r][o]
__device__ float g_Z[B_ * S_ * H_];         // Z[b][t][j]; t=0 slice stays .bss zero forever
__device__ float g_hbuf[2][B_ * H_];        // ping-pong hidden state
__device__ unsigned g_bar;                  // grid barrier counter

// ---------------------------------------------------------------------------
// f32x2 packed fp32 helpers (sm_100+): 2 fp32 MACs per issued instruction.
// ---------------------------------------------------------------------------
static __device__ __forceinline__ void ffma2(unsigned long long& d,
                                             unsigned long long a,
                                             unsigned long long b) {
    asm("fma.rn.f32x2 %0, %1, %2, %0;" : "+l"(d) : "l"(a), "l"(b));
}
static __device__ __forceinline__ unsigned long long pk(float x, float y) {
    unsigned long long r;
    asm("mov.b64 %0, {%1,%2};" : "=l"(r) : "f"(x), "f"(y));
    return r;
}
static __device__ __forceinline__ float2 unpk(unsigned long long v) {
    float2 r;
    asm("mov.b64 {%0,%1}, %2;" : "=f"(r.x), "=f"(r.y) : "l"(v));
    return r;
}

// ---------------------------------------------------------------------------
// Grid barrier: all 128 CTAs resident (1/SM). Monotonic counter, reset by init.
// ---------------------------------------------------------------------------
static __device__ __forceinline__ void gbar(unsigned target) {
    __syncthreads();
    if (threadIdx.x == 0) {
        __threadfence();                     // release prior global writes
        atomicAdd(&g_bar, 1u);
        unsigned v;
        do {
            asm volatile("ld.acquire.gpu.global.u32 %0, [%1];"
                         : "=r"(v) : "l"(&g_bar));
        } while (v < target);
        __threadfence();                     // acquire for the whole block
    }
    __syncthreads();
}

// ---------------------------------------------------------------------------
// Init: h0 -> g_hbuf[0], reset barrier counter
// ---------------------------------------------------------------------------
__global__ void init_k(const float* __restrict__ h0) {
    int i = blockIdx.x * blockDim.x + threadIdx.x;
    if (i < B_ * H_) g_hbuf[0][i] = h0[i];
    if (i == 0) g_bar = 0u;
}

// ---------------------------------------------------------------------------
// GEMM v2: 128x64 tile, 256 threads, 32 outputs/thread (4 rows x 8 cols).
// f32x2 accumulators pair COLUMNS, so w-operand pairs load straight from
// smem with LDS.128 (no dup MOVs); only the a operand is duplicated (4 MOVs
// per 16 FFMA2). Software-pipelined global->reg prefetch across k-steps.
//   MODE 0: U = x[:, t, :] @ Wi^T + bi   rows r = t*64+b (32704 valid rows)
//   MODE 1: logits = Z @ W3^T + b3       rows r = b*512+t (32768 rows)
// ---------------------------------------------------------------------------
template <int MODE>
__global__ __launch_bounds__(256) void gemm2_k(const float* __restrict__ Ap,
                                               const float* __restrict__ W,
                                               const float* __restrict__ bias) {
    constexpr int K = (MODE == 0) ? I_ : H_;
    constexpr int N = (MODE == 0) ? H_ : O_;
    constexpr long VALID_ROWS = (MODE == 0) ? (long)(S_ - 1) * 64 : (long)B_ * S_;

    __shared__ float As[16][132];   // 132: 16B-aligned rows, 2-way STS at worst
    __shared__ float Ws[16][68];

    const int tid = threadIdx.x;
    const int n0 = blockIdx.x * 64;
    const int y  = blockIdx.y;
    const int tx = tid & 7;          // 8-col group
    const int ty = tid >> 3;         // 4-row group

    unsigned long long acc[4][4];
#pragma unroll
    for (int r = 0; r < 4; ++r)
#pragma unroll
        for (int c = 0; c < 4; ++c) acc[r][c] = 0ull;

    float4 rA[2], rW;

    // prefetch k0 = 0
    {
        const int k0 = 0;
#pragma unroll
        for (int e = 0; e < 2; ++e) {
            int i = tid + (e << 8);
            int row = i >> 2, kq = (i & 3) << 2;
            long rg = (long)(y << 7) + row;
            if (MODE == 0) {
                if (rg > VALID_ROWS - 1) rg = VALID_ROWS - 1;
                int b = (int)(rg & 63), t = (int)(rg >> 6);
                rA[e] = *(const float4*)&Ap[((b << 9) + t) * I_ + k0 + kq];
            } else {
                rA[e] = *(const float4*)&g_Z[rg * H_ + k0 + kq];
            }
        }
        int row = tid >> 2, kq = (tid & 3) << 2;
        rW = *(const float4*)&W[(n0 + row) * K + k0 + kq];
    }

    for (int k0 = 0; k0 < K; k0 += 16) {
        // stores regs -> smem (transposed)
#pragma unroll
        for (int e = 0; e < 2; ++e) {
            int i = tid + (e << 8);
            int row = i >> 2, kq = (i & 3) << 2;
            As[kq + 0][row] = rA[e].x; As[kq + 1][row] = rA[e].y;
            As[kq + 2][row] = rA[e].z; As[kq + 3][row] = rA[e].w;
        }
        {
            int row = tid >> 2, kq = (tid & 3) << 2;
            Ws[kq + 0][row] = rW.x; Ws[kq + 1][row] = rW.y;
            Ws[kq + 2][row] = rW.z; Ws[kq + 3][row] = rW.w;
        }
        __syncthreads();

        // prefetch next k-step (hidden behind compute)
        if (k0 + 16 < K) {
            const int kn = k0 + 16;
#pragma unroll
            for (int e = 0; e < 2; ++e) {
                int i = tid + (e << 8);
                int row = i >> 2, kq = (i & 3) << 2;
                long rg = (long)(y << 7) + row;
                if (MODE == 0) {
                    if (rg > VALID_ROWS - 1) rg = VALID_ROWS - 1;
                    int b = (int)(rg & 63), t = (int)(rg >> 6);
                    rA[e] = *(const float4*)&Ap[((b << 9) + t) * I_ + kn + kq];
                } else {
                    rA[e] = *(const float4*)&g_Z[rg * H_ + kn + kq];
                }
            }
            int row = tid >> 2, kq = (tid & 3) << 2;
            rW = *(const float4*)&W[(n0 + row) * K + kn + kq];
        }

#pragma unroll
        for (int kk = 0; kk < 16; ++kk) {
            float4 a4 = *(const float4*)&As[kk][ty << 2];
            ulonglong2 w01 = *(const ulonglong2*)&Ws[kk][tx << 3];
            ulonglong2 w23 = *(const ulonglong2*)&Ws[kk][(tx << 3) + 4];
            unsigned long long d0 = pk(a4.x, a4.x);
            unsigned long long d1 = pk(a4.y, a4.y);
            unsigned long long d2 = pk(a4.z, a4.z);
            unsigned long long d3 = pk(a4.w, a4.w);
            ffma2(acc[0][0], d0, w01.x); ffma2(acc[0][1], d0, w01.y);
            ffma2(acc[0][2], d0, w23.x); ffma2(acc[0][3], d0, w23.y);
            ffma2(acc[1][0], d1, w01.x); ffma2(acc[1][1], d1, w01.y);
            ffma2(acc[1][2], d1, w23.x); ffma2(acc[1][3], d1, w23.y);
            ffma2(acc[2][0], d2, w01.x); ffma2(acc[2][1], d2, w01.y);
            ffma2(acc[2][2], d2, w23.x); ffma2(acc[2][3], d2, w23.y);
            ffma2(acc[3][0], d3, w01.x); ffma2(acc[3][1], d3, w01.y);
            ffma2(acc[3][2], d3, w23.x); ffma2(acc[3][3], d3, w23.y);
        }
        __syncthreads();
    }

    const float4 bb0 = *(const float4*)&bias[n0 + (tx << 3)];
    const float4 bb1 = *(const float4*)&bias[n0 + (tx << 3) + 4];
#pragma unroll
    for (int r = 0; r < 4; ++r) {
        long rg = (long)(y << 7) + (ty << 2) + r;
        if (MODE == 0 && rg >= VALID_ROWS) continue;
        float2 p0 = unpk(acc[r][0]);
        float2 p1 = unpk(acc[r][1]);
        float2 p2 = unpk(acc[r][2]);
        float2 p3 = unpk(acc[r][3]);
        float4 o0 = make_float4(p0.x + bb0.x, p0.y + bb0.y, p1.x + bb0.z, p1.y + bb0.w);
        float4 o1 = make_float4(p2.x + bb1.x, p2.y + bb1.y, p3.x + bb1.z, p3.y + bb1.w);
        long base = rg * N + n0 + (tx << 3);
        *(float4*)&g_U[base]     = o0;
        *(float4*)&g_U[base + 4] = o1;
    }
}

// ---------------------------------------------------------------------------
// Persistent recurrence kernel v3: 512 threads (16 warps = 4/SMSP for
// latency hiding). 128 CTAs = 4 b-groups (16 b) x 32 j-groups (32 j).
// warp w owns k-slice [w*64, w*64+64); lane l owns j = j0 + l.
// Wh[j][k-slice] lives in 32 f32x2 registers for all 512 steps.
// Per step: stage h (64KB), split-k partials via broadcast LDS.128 + FFMA2,
// SMEM reduce (1 output/thread), bias+tanh+fused z/h writes, grid barrier.
// ---------------------------------------------------------------------------
#define RECUR_SMEM ((16 * 1024 + 16 * 16 * 32) * 4)  /* 64KB h + 32KB partials */

__global__ void __launch_bounds__(512, 1) recur_k(const float* __restrict__ Wh,
                                                  const float* __restrict__ bh) {
    extern __shared__ float sm[];
    float* hs   = sm;              // [16][1024]
    float* part = sm + 16 * 1024;  // [16][16][32]  (k-slice, b, j)

    const int tid = threadIdx.x;
    const int w   = tid >> 5;            // warp id 0..15 -> k slice
    const int l   = tid & 31;            // lane -> j
    const int cb  = blockIdx.x;
    const int j0  = (cb & 31) << 5;      // 32 j per CTA
    const int b0  = (cb >> 5) << 4;      // 16 b per CTA
    const int j   = j0 + l;
    const int kw  = w << 6;              // k offset 0,64,...,960

    // Wh[j][kw..kw+63] -> 32 f32x2 registers (held for the whole kernel)
    unsigned long long wreg[32];
    {
        const float* src = &Wh[j * H_ + kw];
#pragma unroll
        for (int q = 0; q < 16; ++q) {
            float4 v = *(const float4*)&src[q << 2];
            wreg[2 * q]     = pk(v.x, v.y);
            wreg[2 * q + 1] = pk(v.z, v.w);
        }
    }

    // reduce-phase mapping: 512 threads = 16 b x 32 j, one output each
    const int rb = tid >> 5;             // 0..15 (batch row)
    const int gb = b0 + rb;
    const float bhj = bh[j];

    for (int m = 0; m < S_; ++m) {
        // ---- stage h_m slice (16 x 1024 floats, coalesced) ----
        const float* hsrc = g_hbuf[m & 1] + (b0 << 10);
        for (int i = tid; i < 4096; i += 512) {
            *(float4*)&hs[i << 2] = *(const float4*)&hsrc[i << 2];
        }
        // prefetch U[m] for this thread's output
        float u0 = 0.f;
        if (m <= S_ - 2) u0 = g_U[((long)m * 64 + gb) * H_ + j];
        __syncthreads();

        // ---- split-k partials over 16 b ----
#pragma unroll 2
        for (int b = 0; b < 16; ++b) {
            const float* hrow = &hs[(b << 10) + kw];
            unsigned long long a0 = 0ull, a1 = 0ull, a2 = 0ull, a3 = 0ull;
#pragma unroll
            for (int q = 0; q < 8; ++q) {
                ulonglong2 h01 = *(const ulonglong2*)&hrow[q << 3];
                ulonglong2 h23 = *(const ulonglong2*)&hrow[(q << 3) + 4];
                ffma2(a0, h01.x, wreg[4 * q]);
                ffma2(a1, h01.y, wreg[4 * q + 1]);
                ffma2(a2, h23.x, wreg[4 * q + 2]);
                ffma2(a3, h23.y, wreg[4 * q + 3]);
            }
            float2 f0 = unpk(a0), f1 = unpk(a1), f2 = unpk(a2), f3 = unpk(a3);
            part[(w << 9) + (b << 5) + l] =
                ((f0.x + f0.y) + (f1.x + f1.y)) + ((f2.x + f2.y) + (f3.x + f3.y));
        }
        __syncthreads();

        // ---- reduce 16 k-slices, bias, tanh, fused z/h writes ----
        {
            float s = 0.f;
#pragma unroll
            for (int ww = 0; ww < 16; ++ww)
                s += part[(ww << 9) + (rb << 5) + l];
            float av = s + bhj;
            if (m >= 1) g_Z[((long)gb * S_ + m) * H_ + j] = tanhf(av);
            if (m <= S_ - 2) g_hbuf[(m + 1) & 1][gb * H_ + j] = tanhf(u0 + av);
        }
        if (m != S_ - 1) gbar((unsigned)(128 * (m + 1)));
    }
}

// ---------------------------------------------------------------------------
// Row softmax over O_=512 cols; warp per row, logits read from g_U (reused).
// ---------------------------------------------------------------------------
__global__ __launch_bounds__(256) void softmax_k(float* __restrict__ out) {
    int r = blockIdx.x * 8 + (threadIdx.x >> 5);
    int l = threadIdx.x & 31;
    const float* row = g_U + (long)r * O_;

    float4 v[4];
    float mx = -3.0e38f;
#pragma unroll
    for (int q = 0; q < 4; ++q) {
        v[q] = *(const float4*)&row[(l + (q << 5)) << 2];
        mx = fmaxf(mx, fmaxf(fmaxf(v[q].x, v[q].y), fmaxf(v[q].z, v[q].w)));
    }
#pragma unroll
    for (int o = 16; o; o >>= 1) mx = fmaxf(mx, __shfl_xor_sync(~0u, mx, o));

    float s = 0.f;
#pragma unroll
    for (int q = 0; q < 4; ++q) {
        v[q].x = expf(v[q].x - mx); v[q].y = expf(v[q].y - mx);
        v[q].z = expf(v[q].z - mx); v[q].w = expf(v[q].w - mx);
        s += (v[q].x + v[q].y) + (v[q].z + v[q].w);
    }
#pragma unroll
    for (int o = 16; o; o >>= 1) s += __shfl_xor_sync(~0u, s, o);
    float inv = 1.0f / s;

#pragma unroll
    for (int q = 0; q < 4; ++q) {
        float4 wv = make_float4(v[q].x * inv, v[q].y * inv, v[q].z * inv, v[q].w * inv);
        *(float4*)&out[(long)r * O_ + ((l + (q << 5)) << 2)] = wv;
    }
}

__global__ void copyht_k(float* __restrict__ dst) {
    int i = blockIdx.x * blockDim.x + threadIdx.x;
    if (i < B_ * H_) dst[i] = g_hbuf[1][i];
}

// ---------------------------------------------------------------------------
// Launch
// ---------------------------------------------------------------------------
extern "C" void kernel_launch(void* const* d_in, const int* in_sizes, int n_in,
                              void* d_out, int out_size) {
    const float* x  = (const float*)d_in[0];
    const float* h0 = (const float*)d_in[1];
    const float* Wi = (const float*)d_in[2];
    const float* bi = (const float*)d_in[3];
    const float* Wh = (const float*)d_in[4];
    const float* bh = (const float*)d_in[5];
    const float* W3 = (const float*)d_in[6];
    const float* b3 = (const float*)d_in[7];
    float* out = (float*)d_out;

    cudaFuncSetAttribute(recur_k, cudaFuncAttributeMaxDynamicSharedMemorySize,
                         RECUR_SMEM);

    // 1. h0 -> state, barrier reset
    init_k<<<(B_ * H_ + 255) / 256, 256>>>(h0);

    // 2. U[t][b][:] = x[b][t][:] @ Wi^T + bi   (t = 0..510)
    gemm2_k<0><<<dim3(H_ / 64, 256), 256>>>(x, Wi, bi);

    // 3. Serial recurrence (persistent, 128 CTAs, 512 steps)
    recur_k<<<128, 512, RECUR_SMEM>>>(Wh, bh);

    // 4. logits = Z @ W3^T + b3   (writes g_U, reused as logits buffer)
    gemm2_k<1><<<dim3(O_ / 64, 256), 256>>>(nullptr, W3, b3);

    // 5. softmax -> d_out
    softmax_k<<<(B_ * S_) / 8, 256>>>(out);

    // 6. final hidden state appended after softmax output
    if (out_size >= B_ * S_ * O_ + B_ * H_) {
        copyht_k<<<(B_ * H_ + 255) / 256, 256>>>(out + (long)B_ * S_ * O_);
    }
}

// round 5
// speedup vs baseline: 1.0989x; 1.0989x over previous
#include <cuda_runtime.h>
#include <cuda_bf16.h>

#define B_ 64
#define S_ 512
#define I_ 512
#define H_ 1024
#define O_ 512

// ---------------------------------------------------------------------------
// Static device scratch (no allocations anywhere)
// ---------------------------------------------------------------------------
__device__ float g_U[(S_ - 1) * B_ * H_];   // U[t][b][j]; later reused as logits[r][o]
__device__ float g_Z[B_ * S_ * H_];         // Z[b][t][j]; t=0 slice stays .bss zero forever
__device__ float g_hbuf[2][B_ * H_];        // ping-pong hidden state
__device__ unsigned g_bar;                  // grid barrier counter

// ---------------------------------------------------------------------------
// f32x2 packed fp32 helpers (sm_100+): 2 fp32 MACs per issued instruction.
// ---------------------------------------------------------------------------
static __device__ __forceinline__ void ffma2(unsigned long long& d,
                                             unsigned long long a,
                                             unsigned long long b) {
    asm("fma.rn.f32x2 %0, %1, %2, %0;" : "+l"(d) : "l"(a), "l"(b));
}
static __device__ __forceinline__ unsigned long long pk(float x, float y) {
    unsigned long long r;
    asm("mov.b64 %0, {%1,%2};" : "=l"(r) : "f"(x), "f"(y));
    return r;
}
static __device__ __forceinline__ float2 unpk(unsigned long long v) {
    float2 r;
    asm("mov.b64 {%0,%1}, %2;" : "=f"(r.x), "=f"(r.y) : "l"(v));
    return r;
}

// ---------------------------------------------------------------------------
// Grid barrier: all 128 CTAs resident (1/SM). Monotonic counter, reset by init.
// ---------------------------------------------------------------------------
static __device__ __forceinline__ void gbar(unsigned target) {
    __syncthreads();
    if (threadIdx.x == 0) {
        __threadfence();                     // release prior global writes
        atomicAdd(&g_bar, 1u);
        unsigned v;
        do {
            asm volatile("ld.acquire.gpu.global.u32 %0, [%1];"
                         : "=r"(v) : "l"(&g_bar));
        } while (v < target);
        __threadfence();                     // acquire for the whole block
    }
    __syncthreads();
}

// ---------------------------------------------------------------------------
// Init: h0 -> g_hbuf[0], reset barrier counter
// ---------------------------------------------------------------------------
__global__ void init_k(const float* __restrict__ h0) {
    int i = blockIdx.x * blockDim.x + threadIdx.x;
    if (i < B_ * H_) g_hbuf[0][i] = h0[i];
    if (i == 0) g_bar = 0u;
}

// ---------------------------------------------------------------------------
// Tiled fp32 NT GEMM (R2 version — known 48% fma, occ 59%).
// 64x64 tile, K-step 16, 256 threads, f32x2 accumulate.
//   MODE 0: U = x[:, t, :] @ Wi^T + bi       (y = t in 0..510, K=512,  N=1024)
//   MODE 1: logits = Z @ W3^T + b3           (y = row-tile,   K=1024, N=512)
// ---------------------------------------------------------------------------
template <int MODE>
__global__ __launch_bounds__(256) void gemm_k(const float* __restrict__ A,
                                              const float* __restrict__ W,
                                              const float* __restrict__ bias) {
    constexpr int K = (MODE == 0) ? I_ : H_;
    constexpr int N = (MODE == 0) ? H_ : O_;

    __shared__ float As[16][68];
    __shared__ float Ws[16][68];

    const int tid = threadIdx.x;
    const int n0 = blockIdx.x * 64;
    const int y  = blockIdx.y;
    const int lm = tid >> 2;        // 0..63 row for loads
    const int kq = (tid & 3) << 2;  // 0,4,8,12

    const int tx = tid & 15;        // 4-col group
    const int ty = tid >> 4;        // 4-row group

    unsigned long long acc[4][2];
#pragma unroll
    for (int i = 0; i < 4; ++i) { acc[i][0] = 0ull; acc[i][1] = 0ull; }

    for (int k0 = 0; k0 < K; k0 += 16) {
        float4 av;
        if (MODE == 0) {
            av = *(const float4*)&A[((lm << 9) + y) * I_ + k0 + kq];
        } else {
            av = *(const float4*)&g_Z[((y << 6) + lm) * H_ + k0 + kq];
        }
        float4 wv = *(const float4*)&W[(n0 + lm) * K + k0 + kq];
        As[kq + 0][lm] = av.x; As[kq + 1][lm] = av.y;
        As[kq + 2][lm] = av.z; As[kq + 3][lm] = av.w;
        Ws[kq + 0][lm] = wv.x; Ws[kq + 1][lm] = wv.y;
        Ws[kq + 2][lm] = wv.z; Ws[kq + 3][lm] = wv.w;
        __syncthreads();

#pragma unroll
        for (int kk = 0; kk < 16; ++kk) {
            ulonglong2 a2 = *(const ulonglong2*)&As[kk][ty << 2];
            float4 w4 = *(const float4*)&Ws[kk][tx << 2];
            unsigned long long w0 = pk(w4.x, w4.x);
            unsigned long long w1 = pk(w4.y, w4.y);
            unsigned long long w2 = pk(w4.z, w4.z);
            unsigned long long w3 = pk(w4.w, w4.w);
            ffma2(acc[0][0], a2.x, w0); ffma2(acc[0][1], a2.y, w0);
            ffma2(acc[1][0], a2.x, w1); ffma2(acc[1][1], a2.y, w1);
            ffma2(acc[2][0], a2.x, w2); ffma2(acc[2][1], a2.y, w2);
            ffma2(acc[3][0], a2.x, w3); ffma2(acc[3][1], a2.y, w3);
        }
        __syncthreads();
    }

    const float4 b4 = *(const float4*)&bias[n0 + (tx << 2)];
#pragma unroll
    for (int p = 0; p < 2; ++p) {
        float2 c0 = unpk(acc[0][p]);
        float2 c1 = unpk(acc[1][p]);
        float2 c2 = unpk(acc[2][p]);
        float2 c3 = unpk(acc[3][p]);
        int r_lo = (ty << 2) + (p << 1);
        float4 o0 = make_float4(c0.x + b4.x, c1.x + b4.y, c2.x + b4.z, c3.x + b4.w);
        float4 o1 = make_float4(c0.y + b4.x, c1.y + b4.y, c2.y + b4.z, c3.y + b4.w);
        long base0 = (long)((y << 6) + r_lo) * N + n0 + (tx << 2);
        *(float4*)&g_U[base0]     = o0;
        *(float4*)&g_U[base0 + N] = o1;
    }
}

// ---------------------------------------------------------------------------
// Persistent recurrence kernel v4:
//  - 512 threads (16 warps = 4/SMSP), 128 CTAs = 4 b-groups x 32 j-groups
//  - warp w owns k-slice [w*64, w*64+64); lane l owns j = j0 + l
//  - Wh[j][k-slice] in 32 f32x2 registers for all 512 steps
//  - h staged with cp.async (LDGSTS, L1-bypass) — no reg round-trip
//  - inner loop interleaves 2 batches: 8 independent acc chains,
//    4 independent broadcast LDS.128 per q-step
// ---------------------------------------------------------------------------
#define RECUR_SMEM ((16 * 1024 + 16 * 16 * 32) * 4)  /* 64KB h + 32KB partials */

__global__ void __launch_bounds__(512, 1) recur_k(const float* __restrict__ Wh,
                                                  const float* __restrict__ bh) {
    extern __shared__ float sm[];
    float* hs   = sm;              // [16][1024]
    float* part = sm + 16 * 1024;  // [16][16][32]  (k-slice, b, j)

    const int tid = threadIdx.x;
    const int w   = tid >> 5;            // warp id 0..15 -> k slice
    const int l   = tid & 31;            // lane -> j
    const int cb  = blockIdx.x;
    const int j0  = (cb & 31) << 5;      // 32 j per CTA
    const int b0  = (cb >> 5) << 4;      // 16 b per CTA
    const int j   = j0 + l;
    const int kw  = w << 6;              // k offset 0,64,...,960

    // Wh[j][kw..kw+63] -> 32 f32x2 registers (held for the whole kernel)
    unsigned long long wreg[32];
    {
        const float* src = &Wh[j * H_ + kw];
#pragma unroll
        for (int q = 0; q < 16; ++q) {
            float4 v = *(const float4*)&src[q << 2];
            wreg[2 * q]     = pk(v.x, v.y);
            wreg[2 * q + 1] = pk(v.z, v.w);
        }
    }

    // reduce-phase mapping: 512 threads = 16 b x 32 j, one output each
    const int rb = tid >> 5;             // 0..15 (batch row)
    const int gb = b0 + rb;
    const float bhj = bh[j];

    const unsigned hs_s = (unsigned)__cvta_generic_to_shared(hs);

    for (int m = 0; m < S_; ++m) {
        // ---- stage h_m slice (16 x 1024 floats) via cp.async ----
        {
            const float* hsrc = g_hbuf[m & 1] + (b0 << 10);
#pragma unroll
            for (int e = 0; e < 8; ++e) {
                int i = tid + (e << 9);           // 0..4095 float4 chunks
                asm volatile("cp.async.cg.shared.global [%0], [%1], 16;"
                             :: "r"(hs_s + (i << 4)), "l"(hsrc + (i << 2)));
            }
            asm volatile("cp.async.commit_group;");
        }
        // prefetch U[m] for this thread's output (overlaps the async fill)
        float u0 = 0.f;
        if (m <= S_ - 2) u0 = g_U[((long)m * 64 + gb) * H_ + j];
        asm volatile("cp.async.wait_group 0;" ::: "memory");
        __syncthreads();

        // ---- split-k partials: 8 pairs of batches, 8 acc chains ----
#pragma unroll 1
        for (int bp = 0; bp < 8; ++bp) {
            const float* hA = &hs[((bp << 1) << 10) + kw];
            const float* hB = &hs[(((bp << 1) + 1) << 10) + kw];
            unsigned long long a0 = 0ull, a1 = 0ull, a2 = 0ull, a3 = 0ull;
            unsigned long long c0 = 0ull, c1 = 0ull, c2 = 0ull, c3 = 0ull;
#pragma unroll
            for (int q = 0; q < 8; ++q) {
                ulonglong2 hA01 = *(const ulonglong2*)&hA[q << 3];
                ulonglong2 hA23 = *(const ulonglong2*)&hA[(q << 3) + 4];
                ulonglong2 hB01 = *(const ulonglong2*)&hB[q << 3];
                ulonglong2 hB23 = *(const ulonglong2*)&hB[(q << 3) + 4];
                ffma2(a0, hA01.x, wreg[4 * q]);
                ffma2(a1, hA01.y, wreg[4 * q + 1]);
                ffma2(a2, hA23.x, wreg[4 * q + 2]);
                ffma2(a3, hA23.y, wreg[4 * q + 3]);
                ffma2(c0, hB01.x, wreg[4 * q]);
                ffma2(c1, hB01.y, wreg[4 * q + 1]);
                ffma2(c2, hB23.x, wreg[4 * q + 2]);
                ffma2(c3, hB23.y, wreg[4 * q + 3]);
            }
            float2 fa0 = unpk(a0), fa1 = unpk(a1), fa2 = unpk(a2), fa3 = unpk(a3);
            float2 fc0 = unpk(c0), fc1 = unpk(c1), fc2 = unpk(c2), fc3 = unpk(c3);
            part[(w << 9) + ((bp << 1) << 5) + l] =
                ((fa0.x + fa0.y) + (fa1.x + fa1.y)) +
                ((fa2.x + fa2.y) + (fa3.x + fa3.y));
            part[(w << 9) + (((bp << 1) + 1) << 5) + l] =
                ((fc0.x + fc0.y) + (fc1.x + fc1.y)) +
                ((fc2.x + fc2.y) + (fc3.x + fc3.y));
        }
        __syncthreads();

        // ---- reduce 16 k-slices, bias, tanh, fused z/h writes ----
        {
            float s = 0.f;
#pragma unroll
            for (int ww = 0; ww < 16; ++ww)
                s += part[(ww << 9) + (rb << 5) + l];
            float av = s + bhj;
            if (m >= 1) g_Z[((long)gb * S_ + m) * H_ + j] = tanhf(av);
            if (m <= S_ - 2) g_hbuf[(m + 1) & 1][gb * H_ + j] = tanhf(u0 + av);
        }
        if (m != S_ - 1) gbar((unsigned)(128 * (m + 1)));
    }
}

// ---------------------------------------------------------------------------
// Row softmax over O_=512 cols; warp per row, logits read from g_U (reused).
// ---------------------------------------------------------------------------
__global__ __launch_bounds__(256) void softmax_k(float* __restrict__ out) {
    int r = blockIdx.x * 8 + (threadIdx.x >> 5);
    int l = threadIdx.x & 31;
    const float* row = g_U + (long)r * O_;

    float4 v[4];
    float mx = -3.0e38f;
#pragma unroll
    for (int q = 0; q < 4; ++q) {
        v[q] = *(const float4*)&row[(l + (q << 5)) << 2];
        mx = fmaxf(mx, fmaxf(fmaxf(v[q].x, v[q].y), fmaxf(v[q].z, v[q].w)));
    }
#pragma unroll
    for (int o = 16; o; o >>= 1) mx = fmaxf(mx, __shfl_xor_sync(~0u, mx, o));

    float s = 0.f;
#pragma unroll
    for (int q = 0; q < 4; ++q) {
        v[q].x = expf(v[q].x - mx); v[q].y = expf(v[q].y - mx);
        v[q].z = expf(v[q].z - mx); v[q].w = expf(v[q].w - mx);
        s += (v[q].x + v[q].y) + (v[q].z + v[q].w);
    }
#pragma unroll
    for (int o = 16; o; o >>= 1) s += __shfl_xor_sync(~0u, s, o);
    float inv = 1.0f / s;

#pragma unroll
    for (int q = 0; q < 4; ++q) {
        float4 wv = make_float4(v[q].x * inv, v[q].y * inv, v[q].z * inv, v[q].w * inv);
        *(float4*)&out[(long)r * O_ + ((l + (q << 5)) << 2)] = wv;
    }
}

__global__ void copyht_k(float* __restrict__ dst) {
    int i = blockIdx.x * blockDim.x + threadIdx.x;
    if (i < B_ * H_) dst[i] = g_hbuf[1][i];
}

// ---------------------------------------------------------------------------
// Launch
// ---------------------------------------------------------------------------
extern "C" void kernel_launch(void* const* d_in, const int* in_sizes, int n_in,
                              void* d_out, int out_size) {
    const float* x  = (const float*)d_in[0];
    const float* h0 = (const float*)d_in[1];
    const float* Wi = (const float*)d_in[2];
    const float* bi = (const float*)d_in[3];
    const float* Wh = (const float*)d_in[4];
    const float* bh = (const float*)d_in[5];
    const float* W3 = (const float*)d_in[6];
    const float* b3 = (const float*)d_in[7];
    float* out = (float*)d_out;

    cudaFuncSetAttribute(recur_k, cudaFuncAttributeMaxDynamicSharedMemorySize,
                         RECUR_SMEM);

    // 1. h0 -> state, barrier reset
    init_k<<<(B_ * H_ + 255) / 256, 256>>>(h0);

    // 2. U[t][b][:] = x[b][t][:] @ Wi^T + bi   (t = 0..510)
    gemm_k<0><<<dim3(H_ / 64, S_ - 1), 256>>>(x, Wi, bi);

    // 3. Serial recurrence (persistent, 128 CTAs, 512 steps)
    recur_k<<<128, 512, RECUR_SMEM>>>(Wh, bh);

    // 4. logits = Z @ W3^T + b3   (writes g_U, reused as logits buffer)
    gemm_k<1><<<dim3(O_ / 64, (B_ * S_) / 64), 256>>>(nullptr, W3, b3);

    // 5. softmax -> d_out
    softmax_k<<<(B_ * S_) / 8, 256>>>(out);

    // 6. final hidden state appended after softmax output
    if (out_size >= B_ * S_ * O_ + B_ * H_) {
        copyht_k<<<(B_ * H_ + 255) / 256, 256>>>(out + (long)B_ * S_ * O_);
    }
}